// round 2
// baseline (speedup 1.0000x reference)
#include <cuda_runtime.h>
#include <stdint.h>

// Problem constants (fixed by the reference):
//   B=16, L=512, NSESS=4, S=512, H=512
// Logical inputs (identified by element count, order-invariant):
//   session_repre        (B,4,S,H) f32    -> 8,388,608 elems (unique)
//   state_transition_mat (B,L,5)   int64/int32 -> 40,960 elems (unique)
//   (utterance_repre 4,194,304 / conversation_repre 8,192 / scalar 1 unused)
// Output: (B, L, 5, H) f32
//
// out[b,l,j,:] = session_repre[b, sess_idx[j], stm[b,l,j]-1, :]
//   with sess_idx = {3,0,1,2,3}
// out[b,l,0,:] = mean_{j=0..3} gathered[b,l,j,:]

#define B_DIM 16
#define L_DIM 512
#define S_DIM 512
#define H_DIM 512
#define H4    (H_DIM / 4)   // 128 float4 per row

__global__ void __launch_bounds__(128, 8)
state_matrix_encoder_kernel(const float4* __restrict__ sess,
                            const int* __restrict__ stm32,
                            float4* __restrict__ out) {
    const int bl = blockIdx.x;              // 0 .. B*L-1
    const int b  = bl >> 9;                 // / L_DIM
    const int t  = threadIdx.x;             // 0 .. 127 (one float4 each)

    // Index dtype detection from data: values are in [1,512] (nonzero).
    // int64 LE layout -> stm32[1] == high word of idx0 == 0.
    // int32 layout    -> stm32[1] == idx1 in [1,512] != 0.
    const int stride = (stm32[1] == 0) ? 2 : 1;   // int32 words per index

    const int base = bl * 5 * stride;
    const int p0 = stm32[base + 0 * stride] - 1;
    const int p1 = stm32[base + 1 * stride] - 1;
    const int p2 = stm32[base + 2 * stride] - 1;
    const int p3 = stm32[base + 3 * stride] - 1;
    const int p4 = stm32[base + 4 * stride] - 1;

    // session_repre row base (in rows): (b*4 + s)*S + pos
    const size_t bbase = (size_t)b * 4 * S_DIM;
    const float4 g0 = sess[(bbase + (size_t)3 * S_DIM + p0) * H4 + t];
    const float4 g1 = sess[(bbase + (size_t)0 * S_DIM + p1) * H4 + t];
    const float4 g2 = sess[(bbase + (size_t)1 * S_DIM + p2) * H4 + t];
    const float4 g3 = sess[(bbase + (size_t)2 * S_DIM + p3) * H4 + t];
    const float4 g4 = sess[(bbase + (size_t)3 * S_DIM + p4) * H4 + t];

    float4 pooled;
    pooled.x = (g0.x + g1.x + g2.x + g3.x) * 0.25f;
    pooled.y = (g0.y + g1.y + g2.y + g3.y) * 0.25f;
    pooled.z = (g0.z + g1.z + g2.z + g3.z) * 0.25f;
    pooled.w = (g0.w + g1.w + g2.w + g3.w) * 0.25f;

    float4* o = out + (size_t)bl * 5 * H4;
    o[0 * H4 + t] = pooled;
    o[1 * H4 + t] = g1;
    o[2 * H4 + t] = g2;
    o[3 * H4 + t] = g3;
    o[4 * H4 + t] = g4;
}

extern "C" void kernel_launch(void* const* d_in, const int* in_sizes, int n_in,
                              void* d_out, int out_size) {
    // Order-invariant input identification by element count.
    const float4* sess  = nullptr;
    const int*    stm32 = nullptr;
    for (int i = 0; i < n_in; i++) {
        if (in_sizes[i] == B_DIM * 4 * S_DIM * H_DIM) sess  = (const float4*)d_in[i];
        else if (in_sizes[i] == B_DIM * L_DIM * 5)    stm32 = (const int*)d_in[i];
    }

    state_matrix_encoder_kernel<<<B_DIM * L_DIM, 128>>>(sess, stm32, (float4*)d_out);
}

// round 3
// speedup vs baseline: 1.0982x; 1.0982x over previous
#include <cuda_runtime.h>
#include <stdint.h>

// Problem constants (fixed by the reference):
//   B=16, L=512, NSESS=4, S=512, H=512
// Logical inputs (identified by element count, order-invariant):
//   session_repre        (B,4,S,H) f32        -> 8,388,608 elems (unique)
//   state_transition_mat (B,L,5)   int64/int32 -> 40,960 elems (unique)
// Output: (B, L, 5, H) f32
//
// out[b,l,j,:] = session_repre[b, sess_idx[j], stm[b,l,j]-1, :]
//   with sess_idx = {3,0,1,2,3}
// out[b,l,0,:] = mean_{j=0..3} gathered[b,l,j,:]

#define B_DIM 16
#define L_DIM 512
#define S_DIM 512
#define H_DIM 512
#define H4    (H_DIM / 4)   // 128 float4 per row
#define PAIRS_PER_BLOCK 2   // 2 (b,l) pairs per 256-thread block

__global__ void __launch_bounds__(256, 4)
state_matrix_encoder_kernel(const float4* __restrict__ sess,
                            const int* __restrict__ stm32,
                            float4* __restrict__ out) {
    const int bl = blockIdx.x * PAIRS_PER_BLOCK + (threadIdx.x >> 7); // (b,l) pair
    const int b  = bl >> 9;                 // / L_DIM
    const int t  = threadIdx.x & 127;       // 0..127 (one float4 each)

    // Index dtype detection from data: values are in [1,512] (nonzero).
    // int64 LE layout -> stm32[1] == high word of idx0 == 0.
    // int32 layout    -> stm32[1] == idx1 in [1,512] != 0.
    const int stride = (stm32[1] == 0) ? 2 : 1;   // int32 words per index

    const int base = bl * 5 * stride;
    const int p0 = stm32[base + 0 * stride] - 1;
    const int p1 = stm32[base + 1 * stride] - 1;
    const int p2 = stm32[base + 2 * stride] - 1;
    const int p3 = stm32[base + 3 * stride] - 1;
    const int p4 = stm32[base + 4 * stride] - 1;

    // session_repre row base (in rows): (b*4 + s)*S + pos. Default (caching)
    // loads — sess (64 MB) should stay L2-resident since output bypasses via stcs.
    const size_t bbase = (size_t)b * 4 * S_DIM;
    const float4 g0 = sess[(bbase + (size_t)3 * S_DIM + p0) * H4 + t];
    const float4 g1 = sess[(bbase + (size_t)0 * S_DIM + p1) * H4 + t];
    const float4 g2 = sess[(bbase + (size_t)1 * S_DIM + p2) * H4 + t];
    const float4 g3 = sess[(bbase + (size_t)2 * S_DIM + p3) * H4 + t];
    const float4 g4 = sess[(bbase + (size_t)3 * S_DIM + p4) * H4 + t];

    float4 pooled;
    pooled.x = (g0.x + g1.x + g2.x + g3.x) * 0.25f;
    pooled.y = (g0.y + g1.y + g2.y + g3.y) * 0.25f;
    pooled.z = (g0.z + g1.z + g2.z + g3.z) * 0.25f;
    pooled.w = (g0.w + g1.w + g2.w + g3.w) * 0.25f;

    // Streaming (evict-first) stores: output is never re-read, don't let it
    // displace session_repre from L2.
    float4* o = out + (size_t)bl * 5 * H4;
    __stcs(o + 0 * H4 + t, pooled);
    __stcs(o + 1 * H4 + t, g1);
    __stcs(o + 2 * H4 + t, g2);
    __stcs(o + 3 * H4 + t, g3);
    __stcs(o + 4 * H4 + t, g4);
}

extern "C" void kernel_launch(void* const* d_in, const int* in_sizes, int n_in,
                              void* d_out, int out_size) {
    // Order-invariant input identification by element count.
    const float4* sess  = nullptr;
    const int*    stm32 = nullptr;
    for (int i = 0; i < n_in; i++) {
        if (in_sizes[i] == B_DIM * 4 * S_DIM * H_DIM) sess  = (const float4*)d_in[i];
        else if (in_sizes[i] == B_DIM * L_DIM * 5)    stm32 = (const int*)d_in[i];
    }

    state_matrix_encoder_kernel<<<(B_DIM * L_DIM) / PAIRS_PER_BLOCK, 256>>>(
        sess, stm32, (float4*)d_out);
}